// round 8
// baseline (speedup 1.0000x reference)
#include <cuda_runtime.h>
#include <math.h>

// ---------------- scratch (device globals; no allocation allowed) ----------------
__device__ float g_c1[24*32*32*32];   // conv1 out [img][32][32][32]
__device__ float g_c2[24*48*16*16];   // conv2 out [img][48][16][16]
__device__ float g_c3[24*64*8*8];     // conv3 out [img][64][8][8]
__device__ float g_logits[24*64];
__device__ float g_u[24*64*128];      // u[img][p][n]
__device__ float g_v[24*64*128];      // v[img][q][n] (includes bg1)
__device__ float g_score[144];        // score[b][j][i]

// ---------------- f32x2 packed helpers (sm_103a FFMA2 path) ----------------
__device__ __forceinline__ unsigned long long pack2(float lo, float hi) {
    unsigned long long r;
    asm("mov.b64 %0, {%1, %2};" : "=l"(r) : "f"(lo), "f"(hi));
    return r;
}
__device__ __forceinline__ void unpack2(unsigned long long v, float& lo, float& hi) {
    asm("mov.b64 {%0, %1}, %2;" : "=f"(lo), "=f"(hi) : "l"(v));
}
__device__ __forceinline__ unsigned long long fma2(unsigned long long a,
                                                   unsigned long long b,
                                                   unsigned long long c) {
    unsigned long long d;
    asm("fma.rn.f32x2 %0, %1, %2, %3;" : "=l"(d) : "l"(a), "l"(b), "l"(c));
    return d;
}

// ---------------- conv1: 3->32, 64x64 -> 32x32, stride 2, pad (0,1) ----------------
// block = fixed (img, ch); weights staged in smem
__global__ void conv1_k(const float* __restrict__ sx, const float* __restrict__ qx,
                        const float* __restrict__ w, const float* __restrict__ bias) {
    __shared__ float ws[27];
    int o = blockIdx.x * 256 + threadIdx.x;
    int ch = (o >> 10) & 31, img = o >> 15;
    if (threadIdx.x < 27) ws[threadIdx.x] = w[ch*27 + threadIdx.x];
    __syncthreads();
    int x = o & 31, y = (o >> 5) & 31;
    int b = img / 6, s = img - b * 6;
    const float* base = (s < 5) ? sx + (size_t)((b*5 + s)*3) * 4096
                                : qx + (size_t)(b*3) * 4096;
    float acc = bias[ch];
    #pragma unroll
    for (int c = 0; c < 3; c++) {
        const float* in = base + c * 4096;
        const float* wp = ws + c * 9;
        #pragma unroll
        for (int kh = 0; kh < 3; kh++) {
            int iy = 2*y + kh; if (iy >= 64) continue;
            #pragma unroll
            for (int kw = 0; kw < 3; kw++) {
                int ix = 2*x + kw; if (ix >= 64) continue;
                acc += in[iy*64 + ix] * wp[kh*3 + kw];
            }
        }
    }
    g_c1[o] = fmaxf(acc, 0.f);
}

// ---------------- conv2: 32->48, 32x32 -> 16x16 ----------------
// block = fixed (img, ch); 288 weights staged in smem
__global__ void conv2_k(const float* __restrict__ w, const float* __restrict__ bias) {
    __shared__ float ws[288];
    int blk = blockIdx.x;              // 0..1151 = img*48 + ch
    int ch = blk % 48, img = blk / 48;
    for (int i = threadIdx.x; i < 288; i += 256) ws[i] = w[ch*288 + i];
    __syncthreads();
    int o = blk * 256 + threadIdx.x;
    int x = o & 15, y = (o >> 4) & 15;
    float acc = bias[ch];
    const float* inb = g_c1 + (size_t)img * 32768;
    for (int c = 0; c < 32; c++) {
        const float* in = inb + c * 1024;
        const float* wp = ws + c * 9;
        #pragma unroll
        for (int kh = 0; kh < 3; kh++) {
            int iy = 2*y + kh; if (iy >= 32) continue;
            #pragma unroll
            for (int kw = 0; kw < 3; kw++) {
                int ix = 2*x + kw; if (ix >= 32) continue;
                acc += in[iy*32 + ix] * wp[kh*3 + kw];
            }
        }
    }
    g_c2[o] = fmaxf(acc, 0.f);
}

// ---------------- conv3: 48->64, 16x16 -> 8x8 ----------------
// block covers (img, 4 consecutive ch); 1728 weights staged in smem
__global__ void conv3_k(const float* __restrict__ w, const float* __restrict__ bias) {
    __shared__ float ws[1728];
    int blk = blockIdx.x;              // 0..383
    int img = blk >> 4;
    int chb = (blk & 15) * 4;
    for (int i = threadIdx.x; i < 1728; i += 256) ws[i] = w[chb*432 + i];
    __syncthreads();
    int o = blk * 256 + threadIdx.x;
    int x = o & 7, y = (o >> 3) & 7, ch = (o >> 6) & 63;
    float acc = bias[ch];
    const float* inb = g_c2 + (size_t)img * 12288;
    const float* wb  = ws + (ch - chb) * 432;
    for (int c = 0; c < 48; c++) {
        const float* in = inb + c * 256;
        const float* wp = wb + c * 9;
        #pragma unroll
        for (int kh = 0; kh < 3; kh++) {
            int iy = 2*y + kh; if (iy >= 16) continue;
            #pragma unroll
            for (int kw = 0; kw < 3; kw++) {
                int ix = 2*x + kw; if (ix >= 16) continue;
                acc += in[iy*16 + ix] * wp[kh*3 + kw];
            }
        }
    }
    g_c3[o] = fmaxf(acc, 0.f);
}

// ---------------- fused uv + poollog: blocks 0..1535 = uv(img,p), 1536..1559 = poollog ----------------
__global__ void uvpool_k(const float* __restrict__ Wg1, const float* __restrict__ bg1,
                         const float* __restrict__ Wlog, const float* __restrict__ blog) {
    int blk = blockIdx.x;
    int tid = threadIdx.x;
    if (blk < 1536) {
        __shared__ float a[66];
        int img = blk >> 6;
        int p   = blk & 63;
        if (tid < 64) a[tid] = g_c3[(size_t)img*4096 + tid*64 + p];
        if (tid == 64) a[64] = (float)(p >> 3) * 0.125f;   // ii[py]
        if (tid == 65) a[65] = (float)(p & 7)  * 0.125f;   // ii[px]
        __syncthreads();
        // threads 0..127 -> u, 128..255 -> v
        int n = tid & 127;
        bool isv = tid >= 128;
        const float* Wbase = Wg1 + (isv ? 66*128 : 0);
        float acc = isv ? bg1[n] : 0.f;
        #pragma unroll 6
        for (int c = 0; c < 66; c++) acc = fmaf(a[c], Wbase[c*128 + n], acc);
        size_t off = (size_t)img * 8192 + p * 128 + n;
        if (isv) g_v[off] = acc; else g_u[off] = acc;
    } else {
        __shared__ float pooled[64];
        int img = blk - 1536;
        int ch = tid >> 2, part = tid & 3;
        const float* fp = g_c3 + (size_t)img * 4096 + ch * 64 + part * 16;
        float s = 0.f;
        #pragma unroll
        for (int i = 0; i < 16; i++) s += fp[i];
        s += __shfl_xor_sync(0xffffffff, s, 1);
        s += __shfl_xor_sync(0xffffffff, s, 2);
        if (part == 0) pooled[ch] = s * (1.f / 64.f);
        __syncthreads();
        if (tid < 64) {
            float l = blog[tid];
            #pragma unroll 8
            for (int cc = 0; cc < 64; cc++) l = fmaf(pooled[cc], Wlog[cc*64 + tid], l);
            g_logits[img*64 + tid] = l;
        }
    }
}

// ---------------- pair kernel: the 9.66 GFLOP core, 384 threads, FFMA2 ----------------
// One CTA per (b,j,i). smem: U[64][128] 32KB, Vs[64][132] 33KB (natural layout, padded),
// Wt[64][128] 32KB, accT[64][384] 96KB, bg2s[64].
#define VS_STRIDE 132
__global__ void __launch_bounds__(384, 1) pair_k(
    const float* __restrict__ Wg2, const float* __restrict__ bg2,
    const float* __restrict__ Wf1, const float* __restrict__ bf1,
    const float* __restrict__ Wf2, const float* __restrict__ bf2) {
    extern __shared__ float sm[];
    float* U    = sm;                    // 8192 floats
    float* Vs   = sm + 8192;             // 64*132 = 8448 floats, Vs[q*132 + k]
    float* Wt   = sm + 8192 + 8448;      // 8192 floats, Wt[n][k]
    float* accT = sm + 8192 + 8448 + 8192;        // 64*384 = 24576 floats
    float* bg2s = sm + 8192 + 8448 + 8192 + 24576; // 64

    int tid = threadIdx.x;
    int blk = blockIdx.x;
    int b = blk / 36; int r = blk - b*36; int j = r / 6; int i = r - j*6;
    const float* up = g_u + (size_t)(b*6 + i) * 8192;
    const float* vp = g_v + (size_t)(b*6 + j) * 8192;

    for (int idx = tid; idx < 8192; idx += 384) {
        U[idx] = up[idx];
        int q = idx >> 7, k = idx & 127;
        Vs[q*VS_STRIDE + k] = vp[idx];
        int kk = idx >> 6, n = idx & 63;
        Wt[n*128 + kk] = Wg2[idx];
    }
    for (int idx = tid; idx < 24576; idx += 384) accT[idx] = 0.f;
    if (tid < 64) bg2s[tid] = bg2[tid];
    __syncthreads();

    int warp = tid >> 5, lane = tid & 31;
    // 128 tiles = p(64) x qh(2), distributed over 12 warps
    for (int t = warp; t < 128; t += 12) {
        int p = t >> 1, qh = t & 1;
        int q = qh*32 + lane;
        const float4* Up = (const float4*)(U + p*128);
        const float4* Vp = (const float4*)(Vs + q*VS_STRIDE);
        unsigned long long h2[64];
        #pragma unroll
        for (int k4 = 0; k4 < 32; k4++) {
            float4 uu = Up[k4];
            float4 vv = Vp[k4];
            float a0 = fmaxf(uu.x + vv.x, 0.f);
            float a1 = fmaxf(uu.y + vv.y, 0.f);
            float a2 = fmaxf(uu.z + vv.z, 0.f);
            float a3 = fmaxf(uu.w + vv.w, 0.f);
            h2[2*k4+0] = pack2(a0, a1);
            h2[2*k4+1] = pack2(a2, a3);
        }
        #pragma unroll 2
        for (int n = 0; n < 64; n++) {
            const ulonglong2* Wp = (const ulonglong2*)(Wt + n*128);
            unsigned long long c0 = pack2(bg2s[n], 0.f);
            unsigned long long c1 = 0ull;
            unsigned long long c2 = 0ull;
            unsigned long long c3 = 0ull;
            #pragma unroll
            for (int k4 = 0; k4 < 16; k4++) {
                ulonglong2 w = Wp[k4];
                c0 = fma2(h2[2*k4+0], w.x, c0);
                c1 = fma2(h2[2*k4+1], w.y, c1);
            }
            #pragma unroll
            for (int k4 = 16; k4 < 32; k4++) {
                ulonglong2 w = Wp[k4];
                c2 = fma2(h2[2*k4+0], w.x, c2);
                c3 = fma2(h2[2*k4+1], w.y, c3);
            }
            float x0, x1, y0, y1, z0, z1, w0, w1;
            unpack2(c0, x0, x1); unpack2(c1, y0, y1);
            unpack2(c2, z0, z1); unpack2(c3, w0, w1);
            float sv = ((x0 + x1) + (y0 + y1)) + ((z0 + z1) + (w0 + w1));
            accT[n*384 + tid] += fmaxf(sv, 0.f);
        }
    }
    __syncthreads();

    // reduce accT -> x_f[64]: stage 1: 6 groups of 64 (U is free now)
    {
        int n = tid & 63, grp = tid >> 6;   // grp 0..5
        float s = 0.f;
        const float* ap = accT + n*384 + grp*64;
        #pragma unroll 8
        for (int t2 = 0; t2 < 64; t2++) s += ap[t2];
        U[grp*64 + n] = s;
    }
    __syncthreads();
    if (tid < 64) {
        float s = 0.f;
        #pragma unroll
        for (int g = 0; g < 6; g++) s += U[g*64 + tid];
        Vs[tid] = s;          // x_f
    }
    __syncthreads();
    if (tid < 16) {
        float s = bf1[tid];
        for (int c = 0; c < 64; c++) s = fmaf(Vs[c], Wf1[c*16 + tid], s);
        Wt[tid] = fmaxf(s, 0.f);
    }
    __syncthreads();
    if (tid == 0) {
        float s = bf2[0];
        for (int t2 = 0; t2 < 16; t2++) s = fmaf(Wt[t2], Wf2[t2], s);
        g_score[blk] = 1.f / (1.f + __expf(-s));
    }
}

// ---------------- final losses: single block ----------------
__global__ void final_k(const int* __restrict__ sy, const int* __restrict__ qy,
                        float* __restrict__ out) {
    __shared__ float sP[144], sY[144], scls[24];
    __shared__ int slab[24];
    int tid = threadIdx.x;
    if (tid < 144) sP[tid] = g_score[tid];
    if (tid < 24) {
        int b = tid / 6, s = tid - b*6;
        slab[tid] = (s < 5) ? sy[b*5 + s] : qy[b];
    }
    __syncthreads();
    if (tid < 24) {
        const float* row = g_logits + tid*64;
        float m = row[0];
        for (int n = 1; n < 64; n++) m = fmaxf(m, row[n]);
        float se = 0.f;
        for (int n = 0; n < 64; n++) se += __expf(row[n] - m);
        float lse = m + __logf(se);
        scls[tid] = -(row[slab[tid]] - lse);
    }
    if (tid < 144) {
        int b = tid / 36, r = tid - b*36; int jj = r / 6, ii = r - jj*6;
        sY[tid] = (slab[b*6 + jj] == slab[b*6 + ii]) ? 1.f : 0.f;
    }
    __syncthreads();
    if (tid == 0) {
        float cls = 0.f;
        for (int r2 = 0; r2 < 24; r2++) cls += scls[r2];
        cls /= 24.f;
        float euc = 0.f;
        for (int t = 0; t < 144; t++) { float d = sP[t] - sY[t]; euc += d*d; }
        euc /= 144.f;
        float syml = 0.f;
        for (int b2 = 0; b2 < 4; b2++) {
            float s2 = 0.f, a2 = 0.f;
            for (int jj = 0; jj < 6; jj++)
                for (int ii = 0; ii < 6; ii++) {
                    float pa = sP[b2*36 + jj*6 + ii];
                    float pb = sP[b2*36 + ii*6 + jj];
                    float sv = 0.5f*(pa + pb), av = 0.5f*(pa - pb);
                    s2 += sv*sv; a2 += av*av;
                }
            float sn = sqrtf(s2), an = sqrtf(a2);
            syml += (sn - an) / (sn + an);
        }
        syml *= 0.25f;
        out[0] = cls;
        out[1] = euc - 0.1f * syml;
        out[2] = syml;
    }
}

// ---------------- launch ----------------
extern "C" void kernel_launch(void* const* d_in, const int* in_sizes, int n_in,
                              void* d_out, int out_size) {
    const float* sx   = (const float*)d_in[0];
    const int*   sy   = (const int*)  d_in[1];
    const float* qx   = (const float*)d_in[2];
    const int*   qy   = (const int*)  d_in[3];
    const float* k1   = (const float*)d_in[4];
    const float* bc1  = (const float*)d_in[5];
    const float* k2   = (const float*)d_in[6];
    const float* bc2  = (const float*)d_in[7];
    const float* k3   = (const float*)d_in[8];
    const float* bc3  = (const float*)d_in[9];
    const float* Wlog = (const float*)d_in[10];
    const float* blog = (const float*)d_in[11];
    const float* Wg1  = (const float*)d_in[12];
    const float* bg1  = (const float*)d_in[13];
    const float* Wg2  = (const float*)d_in[14];
    const float* bg2  = (const float*)d_in[15];
    const float* Wf1  = (const float*)d_in[16];
    const float* bf1  = (const float*)d_in[17];
    const float* Wf2  = (const float*)d_in[18];
    const float* bf2  = (const float*)d_in[19];
    float* out = (float*)d_out;

    const int pair_smem = (8192 + 8448 + 8192 + 24576 + 64) * sizeof(float); // 197888 B
    cudaFuncSetAttribute(pair_k, cudaFuncAttributeMaxDynamicSharedMemorySize, pair_smem);

    conv1_k<<<3072, 256>>>(sx, qx, k1, bc1);
    conv2_k<<<1152, 256>>>(k2, bc2);
    conv3_k<<< 384, 256>>>(k3, bc3);
    uvpool_k<<<1560, 256>>>(Wg1, bg1, Wlog, blog);
    pair_k<<<144, 384, pair_smem>>>(Wg2, bg2, Wf1, bf1, Wf2, bf2);
    final_k<<<1, 160>>>(sy, qy, out);
}

// round 9
// speedup vs baseline: 1.4676x; 1.4676x over previous
#include <cuda_runtime.h>
#include <math.h>

// ---------------- scratch (device globals; no allocation allowed) ----------------
__device__ float g_c1[24*32*32*32];   // conv1 out [img][32][32][32]
__device__ float g_c2[24*48*16*16];   // conv2 out [img][48][16][16]
__device__ float g_c3[24*64*8*8];     // conv3 out [img][64][8][8]
__device__ float g_logits[24*64];
__device__ float g_u[24*64*128];      // u[img][p][n]
__device__ float g_v[24*64*128];      // v[img][q][n] (includes bg1)
__device__ float g_score[144];        // score[b][j][i]

// ---------------- f32x2 packed helpers (sm_103a FFMA2 path) ----------------
__device__ __forceinline__ unsigned long long pack2(float lo, float hi) {
    unsigned long long r;
    asm("mov.b64 %0, {%1, %2};" : "=l"(r) : "f"(lo), "f"(hi));
    return r;
}
__device__ __forceinline__ void unpack2(unsigned long long v, float& lo, float& hi) {
    asm("mov.b64 {%0, %1}, %2;" : "=f"(lo), "=f"(hi) : "l"(v));
}
__device__ __forceinline__ unsigned long long fma2(unsigned long long a,
                                                   unsigned long long b,
                                                   unsigned long long c) {
    unsigned long long d;
    asm("fma.rn.f32x2 %0, %1, %2, %3;" : "=l"(d) : "l"(a), "l"(b), "l"(c));
    return d;
}

// ---------------- conv1: 3->32, 64x64 -> 32x32, stride 2, pad (0,1) ----------------
__global__ void conv1_k(const float* __restrict__ sx, const float* __restrict__ qx,
                        const float* __restrict__ w, const float* __restrict__ bias) {
    __shared__ float ws[27];
    int o = blockIdx.x * 256 + threadIdx.x;
    int ch = (o >> 10) & 31, img = o >> 15;
    if (threadIdx.x < 27) ws[threadIdx.x] = w[ch*27 + threadIdx.x];
    __syncthreads();
    int x = o & 31, y = (o >> 5) & 31;
    int b = img / 6, s = img - b * 6;
    const float* base = (s < 5) ? sx + (size_t)((b*5 + s)*3) * 4096
                                : qx + (size_t)(b*3) * 4096;
    float acc = bias[ch];
    #pragma unroll
    for (int c = 0; c < 3; c++) {
        const float* in = base + c * 4096;
        const float* wp = ws + c * 9;
        #pragma unroll
        for (int kh = 0; kh < 3; kh++) {
            int iy = 2*y + kh; if (iy >= 64) continue;
            #pragma unroll
            for (int kw = 0; kw < 3; kw++) {
                int ix = 2*x + kw; if (ix >= 64) continue;
                acc += in[iy*64 + ix] * wp[kh*3 + kw];
            }
        }
    }
    g_c1[o] = fmaxf(acc, 0.f);
}

// ---------------- conv2: 32->48, 32x32 -> 16x16 ----------------
__global__ void conv2_k(const float* __restrict__ w, const float* __restrict__ bias) {
    __shared__ float ws[288];
    int blk = blockIdx.x;              // 0..1151 = img*48 + ch
    int ch = blk % 48, img = blk / 48;
    for (int i = threadIdx.x; i < 288; i += 256) ws[i] = w[ch*288 + i];
    __syncthreads();
    int o = blk * 256 + threadIdx.x;
    int x = o & 15, y = (o >> 4) & 15;
    float acc = bias[ch];
    const float* inb = g_c1 + (size_t)img * 32768;
    for (int c = 0; c < 32; c++) {
        const float* in = inb + c * 1024;
        const float* wp = ws + c * 9;
        #pragma unroll
        for (int kh = 0; kh < 3; kh++) {
            int iy = 2*y + kh; if (iy >= 32) continue;
            #pragma unroll
            for (int kw = 0; kw < 3; kw++) {
                int ix = 2*x + kw; if (ix >= 32) continue;
                acc += in[iy*32 + ix] * wp[kh*3 + kw];
            }
        }
    }
    g_c2[o] = fmaxf(acc, 0.f);
}

// ---------------- conv3: 48->64, 16x16 -> 8x8 ----------------
__global__ void conv3_k(const float* __restrict__ w, const float* __restrict__ bias) {
    __shared__ float ws[1728];
    int blk = blockIdx.x;              // 0..383
    int img = blk >> 4;
    int chb = (blk & 15) * 4;
    for (int i = threadIdx.x; i < 1728; i += 256) ws[i] = w[chb*432 + i];
    __syncthreads();
    int o = blk * 256 + threadIdx.x;
    int x = o & 7, y = (o >> 3) & 7, ch = (o >> 6) & 63;
    float acc = bias[ch];
    const float* inb = g_c2 + (size_t)img * 12288;
    const float* wb  = ws + (ch - chb) * 432;
    for (int c = 0; c < 48; c++) {
        const float* in = inb + c * 256;
        const float* wp = wb + c * 9;
        #pragma unroll
        for (int kh = 0; kh < 3; kh++) {
            int iy = 2*y + kh; if (iy >= 16) continue;
            #pragma unroll
            for (int kw = 0; kw < 3; kw++) {
                int ix = 2*x + kw; if (ix >= 16) continue;
                acc += in[iy*16 + ix] * wp[kh*3 + kw];
            }
        }
    }
    g_c3[o] = fmaxf(acc, 0.f);
}

// ---------------- fused uv + poollog ----------------
__global__ void uvpool_k(const float* __restrict__ Wg1, const float* __restrict__ bg1,
                         const float* __restrict__ Wlog, const float* __restrict__ blog) {
    int blk = blockIdx.x;
    int tid = threadIdx.x;
    if (blk < 1536) {
        __shared__ float a[66];
        int img = blk >> 6;
        int p   = blk & 63;
        if (tid < 64) a[tid] = g_c3[(size_t)img*4096 + tid*64 + p];
        if (tid == 64) a[64] = (float)(p >> 3) * 0.125f;   // ii[py]
        if (tid == 65) a[65] = (float)(p & 7)  * 0.125f;   // ii[px]
        __syncthreads();
        int n = tid & 127;
        bool isv = tid >= 128;
        const float* Wbase = Wg1 + (isv ? 66*128 : 0);
        float acc = isv ? bg1[n] : 0.f;
        #pragma unroll 6
        for (int c = 0; c < 66; c++) acc = fmaf(a[c], Wbase[c*128 + n], acc);
        size_t off = (size_t)img * 8192 + p * 128 + n;
        if (isv) g_v[off] = acc; else g_u[off] = acc;
    } else {
        __shared__ float pooled[64];
        int img = blk - 1536;
        int ch = tid >> 2, part = tid & 3;
        const float* fp = g_c3 + (size_t)img * 4096 + ch * 64 + part * 16;
        float s = 0.f;
        #pragma unroll
        for (int i = 0; i < 16; i++) s += fp[i];
        s += __shfl_xor_sync(0xffffffff, s, 1);
        s += __shfl_xor_sync(0xffffffff, s, 2);
        if (part == 0) pooled[ch] = s * (1.f / 64.f);
        __syncthreads();
        if (tid < 64) {
            float l = blog[tid];
            #pragma unroll 8
            for (int cc = 0; cc < 64; cc++) l = fmaf(pooled[cc], Wlog[cc*64 + tid], l);
            g_logits[img*64 + tid] = l;
        }
    }
}

// ---------------- pair kernel: smem-tiled GEMM with register accumulators ----------------
// One CTA per (b,j,i), 256 threads. smem: U[64][128], Vs[64][128], Ws[128][64] (natural),
// H[64][128], bg2s[64]. Per p: build H = relu(u_p + v_q), GEMM H x Ws, relu+bias, sum.
__global__ void __launch_bounds__(256, 1) pair_k(
    const float* __restrict__ Wg2, const float* __restrict__ bg2,
    const float* __restrict__ Wf1, const float* __restrict__ bf1,
    const float* __restrict__ Wf2, const float* __restrict__ bf2) {
    extern __shared__ float sm[];
    float* U    = sm;                 // 8192  U[p][k]
    float* Vs   = sm + 8192;          // 8192  Vs[q][k]
    float* Ws   = sm + 16384;         // 8192  Ws[k][n]  (natural Wg2 layout)
    float* H    = sm + 24576;         // 8192  H[q][k]
    float* bg2s = sm + 32768;         // 64

    int tid = threadIdx.x;
    int blk = blockIdx.x;
    int b = blk / 36; int r = blk - b*36; int j = r / 6; int i = r - j*6;
    const float* up = g_u + (size_t)(b*6 + i) * 8192;
    const float* vp = g_v + (size_t)(b*6 + j) * 8192;

    for (int idx = tid; idx < 8192; idx += 256) {
        U[idx]  = up[idx];
        Vs[idx] = vp[idx];
        Ws[idx] = Wg2[idx];           // Wg2 is [k=128][n=64] row-major
    }
    if (tid < 64) bg2s[tid] = bg2[tid];
    __syncthreads();

    // thread tile: 4 q x 4 n
    int ng = tid & 15, qg = tid >> 4;          // 16 x 16
    int n0 = ng * 4, q0 = qg * 4;
    float bb0 = bg2s[n0+0], bb1 = bg2s[n0+1], bb2 = bg2s[n0+2], bb3 = bg2s[n0+3];

    // build-phase mapping: fixed k0 per thread, 32 q's
    int k0 = tid & 127, qb = tid >> 7;         // qb in {0,1}

    float run[16];
    #pragma unroll
    for (int t = 0; t < 16; t++) run[t] = 0.f;

    const float4* H4 = (const float4*)H;
    const ulonglong2* W2 = (const ulonglong2*)Ws;   // row k = 16 ulonglong2

    for (int p = 0; p < 64; p++) {
        // ---- build H[q][k] = relu(U[p][k] + Vs[q][k]) ----
        float upk = U[p*128 + k0];
        __syncthreads();              // previous GEMM done with H
        #pragma unroll 4
        for (int t = 0; t < 32; t++) {
            int q = qb + 2*t;
            H[q*128 + k0] = fmaxf(upk + Vs[q*128 + k0], 0.f);
        }
        __syncthreads();

        // ---- GEMM: acc2[qi][np] = sum_k H[q0+qi][k] * Ws[k][n0 + 2np..+1] ----
        unsigned long long a00=0, a01=0, a10=0, a11=0, a20=0, a21=0, a30=0, a31=0;
        #pragma unroll 2
        for (int k4 = 0; k4 < 32; k4++) {
            float4 h0 = H4[(q0+0)*32 + k4];
            float4 h1 = H4[(q0+1)*32 + k4];
            float4 h2 = H4[(q0+2)*32 + k4];
            float4 h3 = H4[(q0+3)*32 + k4];
            ulonglong2 w0 = W2[(4*k4+0)*16 + ng];
            ulonglong2 w1 = W2[(4*k4+1)*16 + ng];
            ulonglong2 w2 = W2[(4*k4+2)*16 + ng];
            ulonglong2 w3 = W2[(4*k4+3)*16 + ng];
            unsigned long long d;
            d = pack2(h0.x, h0.x); a00 = fma2(d, w0.x, a00); a01 = fma2(d, w0.y, a01);
            d = pack2(h1.x, h1.x); a10 = fma2(d, w0.x, a10); a11 = fma2(d, w0.y, a11);
            d = pack2(h2.x, h2.x); a20 = fma2(d, w0.x, a20); a21 = fma2(d, w0.y, a21);
            d = pack2(h3.x, h3.x); a30 = fma2(d, w0.x, a30); a31 = fma2(d, w0.y, a31);
            d = pack2(h0.y, h0.y); a00 = fma2(d, w1.x, a00); a01 = fma2(d, w1.y, a01);
            d = pack2(h1.y, h1.y); a10 = fma2(d, w1.x, a10); a11 = fma2(d, w1.y, a11);
            d = pack2(h2.y, h2.y); a20 = fma2(d, w1.x, a20); a21 = fma2(d, w1.y, a21);
            d = pack2(h3.y, h3.y); a30 = fma2(d, w1.x, a30); a31 = fma2(d, w1.y, a31);
            d = pack2(h0.z, h0.z); a00 = fma2(d, w2.x, a00); a01 = fma2(d, w2.y, a01);
            d = pack2(h1.z, h1.z); a10 = fma2(d, w2.x, a10); a11 = fma2(d, w2.y, a11);
            d = pack2(h2.z, h2.z); a20 = fma2(d, w2.x, a20); a21 = fma2(d, w2.y, a21);
            d = pack2(h3.z, h3.z); a30 = fma2(d, w2.x, a30); a31 = fma2(d, w2.y, a31);
            d = pack2(h0.w, h0.w); a00 = fma2(d, w3.x, a00); a01 = fma2(d, w3.y, a01);
            d = pack2(h1.w, h1.w); a10 = fma2(d, w3.x, a10); a11 = fma2(d, w3.y, a11);
            d = pack2(h2.w, h2.w); a20 = fma2(d, w3.x, a20); a21 = fma2(d, w3.y, a21);
            d = pack2(h3.w, h3.w); a30 = fma2(d, w3.x, a30); a31 = fma2(d, w3.y, a31);
        }
        // ---- bias + relu + running sum (registers only) ----
        float e0, e1;
        unpack2(a00, e0, e1); run[0]  += fmaxf(e0 + bb0, 0.f); run[1]  += fmaxf(e1 + bb1, 0.f);
        unpack2(a01, e0, e1); run[2]  += fmaxf(e0 + bb2, 0.f); run[3]  += fmaxf(e1 + bb3, 0.f);
        unpack2(a10, e0, e1); run[4]  += fmaxf(e0 + bb0, 0.f); run[5]  += fmaxf(e1 + bb1, 0.f);
        unpack2(a11, e0, e1); run[6]  += fmaxf(e0 + bb2, 0.f); run[7]  += fmaxf(e1 + bb3, 0.f);
        unpack2(a20, e0, e1); run[8]  += fmaxf(e0 + bb0, 0.f); run[9]  += fmaxf(e1 + bb1, 0.f);
        unpack2(a21, e0, e1); run[10] += fmaxf(e0 + bb2, 0.f); run[11] += fmaxf(e1 + bb3, 0.f);
        unpack2(a30, e0, e1); run[12] += fmaxf(e0 + bb0, 0.f); run[13] += fmaxf(e1 + bb1, 0.f);
        unpack2(a31, e0, e1); run[14] += fmaxf(e0 + bb2, 0.f); run[15] += fmaxf(e1 + bb3, 0.f);
    }
    __syncthreads();

    // ---- reduce run -> x_f[64] via red[n][q] (reuse Vs, stride 65) ----
    float* red = Vs;
    #pragma unroll
    for (int qi = 0; qi < 4; qi++)
        #pragma unroll
        for (int ni = 0; ni < 4; ni++)
            red[(n0+ni)*65 + (q0+qi)] = run[qi*4 + ni];
    __syncthreads();
    if (tid < 64) {
        float s = 0.f;
        const float* rp = red + tid*65;
        #pragma unroll 8
        for (int q = 0; q < 64; q++) s += rp[q];
        U[tid] = s;           // x_f
    }
    __syncthreads();
    if (tid < 16) {
        float s = bf1[tid];
        for (int c = 0; c < 64; c++) s = fmaf(U[c], Wf1[c*16 + tid], s);
        H[tid] = fmaxf(s, 0.f);
    }
    __syncthreads();
    if (tid == 0) {
        float s = bf2[0];
        for (int t2 = 0; t2 < 16; t2++) s = fmaf(H[t2], Wf2[t2], s);
        g_score[blk] = 1.f / (1.f + __expf(-s));
    }
}

// ---------------- final losses: single block ----------------
__global__ void final_k(const int* __restrict__ sy, const int* __restrict__ qy,
                        float* __restrict__ out) {
    __shared__ float sP[144], sY[144], scls[24];
    __shared__ int slab[24];
    int tid = threadIdx.x;
    if (tid < 144) sP[tid] = g_score[tid];
    if (tid < 24) {
        int b = tid / 6, s = tid - b*6;
        slab[tid] = (s < 5) ? sy[b*5 + s] : qy[b];
    }
    __syncthreads();
    if (tid < 24) {
        const float* row = g_logits + tid*64;
        float m = row[0];
        for (int n = 1; n < 64; n++) m = fmaxf(m, row[n]);
        float se = 0.f;
        for (int n = 0; n < 64; n++) se += __expf(row[n] - m);
        float lse = m + __logf(se);
        scls[tid] = -(row[slab[tid]] - lse);
    }
    if (tid < 144) {
        int b = tid / 36, r = tid - b*36; int jj = r / 6, ii = r - jj*6;
        sY[tid] = (slab[b*6 + jj] == slab[b*6 + ii]) ? 1.f : 0.f;
    }
    __syncthreads();
    if (tid == 0) {
        float cls = 0.f;
        for (int r2 = 0; r2 < 24; r2++) cls += scls[r2];
        cls /= 24.f;
        float euc = 0.f;
        for (int t = 0; t < 144; t++) { float d = sP[t] - sY[t]; euc += d*d; }
        euc /= 144.f;
        float syml = 0.f;
        for (int b2 = 0; b2 < 4; b2++) {
            float s2 = 0.f, a2 = 0.f;
            for (int jj = 0; jj < 6; jj++)
                for (int ii = 0; ii < 6; ii++) {
                    float pa = sP[b2*36 + jj*6 + ii];
                    float pb = sP[b2*36 + ii*6 + jj];
                    float sv = 0.5f*(pa + pb), av = 0.5f*(pa - pb);
                    s2 += sv*sv; a2 += av*av;
                }
            float sn = sqrtf(s2), an = sqrtf(a2);
            syml += (sn - an) / (sn + an);
        }
        syml *= 0.25f;
        out[0] = cls;
        out[1] = euc - 0.1f * syml;
        out[2] = syml;
    }
}

// ---------------- launch ----------------
extern "C" void kernel_launch(void* const* d_in, const int* in_sizes, int n_in,
                              void* d_out, int out_size) {
    const float* sx   = (const float*)d_in[0];
    const int*   sy   = (const int*)  d_in[1];
    const float* qx   = (const float*)d_in[2];
    const int*   qy   = (const int*)  d_in[3];
    const float* k1   = (const float*)d_in[4];
    const float* bc1  = (const float*)d_in[5];
    const float* k2   = (const float*)d_in[6];
    const float* bc2  = (const float*)d_in[7];
    const float* k3   = (const float*)d_in[8];
    const float* bc3  = (const float*)d_in[9];
    const float* Wlog = (const float*)d_in[10];
    const float* blog = (const float*)d_in[11];
    const float* Wg1  = (const float*)d_in[12];
    const float* bg1  = (const float*)d_in[13];
    const float* Wg2  = (const float*)d_in[14];
    const float* bg2  = (const float*)d_in[15];
    const float* Wf1  = (const float*)d_in[16];
    const float* bf1  = (const float*)d_in[17];
    const float* Wf2  = (const float*)d_in[18];
    const float* bf2  = (const float*)d_in[19];
    float* out = (float*)d_out;

    const int pair_smem = (8192*4 + 64) * sizeof(float); // 131328 B
    cudaFuncSetAttribute(pair_k, cudaFuncAttributeMaxDynamicSharedMemorySize, pair_smem);

    conv1_k<<<3072, 256>>>(sx, qx, k1, bc1);
    conv2_k<<<1152, 256>>>(k2, bc2);
    conv3_k<<< 384, 256>>>(k3, bc3);
    uvpool_k<<<1560, 256>>>(Wg1, bg1, Wlog, blog);
    pair_k<<<144, 256, pair_smem>>>(Wg2, bg2, Wf1, bf1, Wf2, bf2);
    final_k<<<1, 160>>>(sy, qy, out);
}

// round 11
// speedup vs baseline: 1.5783x; 1.0754x over previous
#include <cuda_runtime.h>
#include <math.h>

// ---------------- scratch (device globals; no allocation allowed) ----------------
__device__ float g_c1[24*32*32*32];   // conv1 out [img][32][32][32]
__device__ float g_c2[24*48*16*16];   // conv2 out [img][48][16][16]
__device__ float g_c3[24*64*8*8];     // conv3 out [img][64][8][8]
__device__ float g_logits[24*64];
__device__ float g_u[24*64*128];      // u[img][p][n]
__device__ float g_v[24*64*128];      // v[img][q][n] (includes bg1)
__device__ float g_score[144];        // score[b][j][i]

// ---------------- f32x2 packed helpers (sm_103a FFMA2 path) ----------------
__device__ __forceinline__ void unpack2(unsigned long long v, float& lo, float& hi) {
    asm("mov.b64 {%0, %1}, %2;" : "=f"(lo), "=f"(hi) : "l"(v));
}
__device__ __forceinline__ unsigned long long fma2(unsigned long long a,
                                                   unsigned long long b,
                                                   unsigned long long c) {
    unsigned long long d;
    asm("fma.rn.f32x2 %0, %1, %2, %3;" : "=l"(d) : "l"(a), "l"(b), "l"(c));
    return d;
}

// ---------------- conv1: 3->32, 64x64 -> 32x32, stride 2, pad (0,1) ----------------
__global__ void conv1_k(const float* __restrict__ sx, const float* __restrict__ qx,
                        const float* __restrict__ w, const float* __restrict__ bias) {
    __shared__ float ws[27];
    int o = blockIdx.x * 256 + threadIdx.x;
    int ch = (o >> 10) & 31, img = o >> 15;
    if (threadIdx.x < 27) ws[threadIdx.x] = w[ch*27 + threadIdx.x];
    __syncthreads();
    int x = o & 31, y = (o >> 5) & 31;
    int b = img / 6, s = img - b * 6;
    const float* base = (s < 5) ? sx + (size_t)((b*5 + s)*3) * 4096
                                : qx + (size_t)(b*3) * 4096;
    float acc = bias[ch];
    #pragma unroll
    for (int c = 0; c < 3; c++) {
        const float* in = base + c * 4096;
        const float* wp = ws + c * 9;
        #pragma unroll
        for (int kh = 0; kh < 3; kh++) {
            int iy = 2*y + kh; if (iy >= 64) continue;
            #pragma unroll
            for (int kw = 0; kw < 3; kw++) {
                int ix = 2*x + kw; if (ix >= 64) continue;
                acc += in[iy*64 + ix] * wp[kh*3 + kw];
            }
        }
    }
    g_c1[o] = fmaxf(acc, 0.f);
}

// ---------------- conv2: 32->48, 32x32 -> 16x16 ----------------
__global__ void conv2_k(const float* __restrict__ w, const float* __restrict__ bias) {
    __shared__ float ws[288];
    int blk = blockIdx.x;              // 0..1151 = img*48 + ch
    int ch = blk % 48, img = blk / 48;
    for (int i = threadIdx.x; i < 288; i += 256) ws[i] = w[ch*288 + i];
    __syncthreads();
    int o = blk * 256 + threadIdx.x;
    int x = o & 15, y = (o >> 4) & 15;
    float acc = bias[ch];
    const float* inb = g_c1 + (size_t)img * 32768;
    for (int c = 0; c < 32; c++) {
        const float* in = inb + c * 1024;
        const float* wp = ws + c * 9;
        #pragma unroll
        for (int kh = 0; kh < 3; kh++) {
            int iy = 2*y + kh; if (iy >= 32) continue;
            #pragma unroll
            for (int kw = 0; kw < 3; kw++) {
                int ix = 2*x + kw; if (ix >= 32) continue;
                acc += in[iy*32 + ix] * wp[kh*3 + kw];
            }
        }
    }
    g_c2[o] = fmaxf(acc, 0.f);
}

// ---------------- conv3: 48->64, 16x16 -> 8x8 ----------------
__global__ void conv3_k(const float* __restrict__ w, const float* __restrict__ bias) {
    __shared__ float ws[1728];
    int blk = blockIdx.x;              // 0..383
    int img = blk >> 4;
    int chb = (blk & 15) * 4;
    for (int i = threadIdx.x; i < 1728; i += 256) ws[i] = w[chb*432 + i];
    __syncthreads();
    int o = blk * 256 + threadIdx.x;
    int x = o & 7, y = (o >> 3) & 7, ch = (o >> 6) & 63;
    float acc = bias[ch];
    const float* inb = g_c2 + (size_t)img * 12288;
    const float* wb  = ws + (ch - chb) * 432;
    for (int c = 0; c < 48; c++) {
        const float* in = inb + c * 256;
        const float* wp = wb + c * 9;
        #pragma unroll
        for (int kh = 0; kh < 3; kh++) {
            int iy = 2*y + kh; if (iy >= 16) continue;
            #pragma unroll
            for (int kw = 0; kw < 3; kw++) {
                int ix = 2*x + kw; if (ix >= 16) continue;
                acc += in[iy*16 + ix] * wp[kh*3 + kw];
            }
        }
    }
    g_c3[o] = fmaxf(acc, 0.f);
}

// ---------------- fused uv + poollog ----------------
__global__ void uvpool_k(const float* __restrict__ Wg1, const float* __restrict__ bg1,
                         const float* __restrict__ Wlog, const float* __restrict__ blog) {
    int blk = blockIdx.x;
    int tid = threadIdx.x;
    if (blk < 1536) {
        __shared__ float a[66];
        int img = blk >> 6;
        int p   = blk & 63;
        if (tid < 64) a[tid] = g_c3[(size_t)img*4096 + tid*64 + p];
        if (tid == 64) a[64] = (float)(p >> 3) * 0.125f;   // ii[py]
        if (tid == 65) a[65] = (float)(p & 7)  * 0.125f;   // ii[px]
        __syncthreads();
        int n = tid & 127;
        bool isv = tid >= 128;
        const float* Wbase = Wg1 + (isv ? 66*128 : 0);
        float acc = isv ? bg1[n] : 0.f;
        #pragma unroll 6
        for (int c = 0; c < 66; c++) acc = fmaf(a[c], Wbase[c*128 + n], acc);
        size_t off = (size_t)img * 8192 + p * 128 + n;
        if (isv) g_v[off] = acc; else g_u[off] = acc;
    } else {
        __shared__ float pooled[64];
        int img = blk - 1536;
        int ch = tid >> 2, part = tid & 3;
        const float* fp = g_c3 + (size_t)img * 4096 + ch * 64 + part * 16;
        float s = 0.f;
        #pragma unroll
        for (int i = 0; i < 16; i++) s += fp[i];
        s += __shfl_xor_sync(0xffffffff, s, 1);
        s += __shfl_xor_sync(0xffffffff, s, 2);
        if (part == 0) pooled[ch] = s * (1.f / 64.f);
        __syncthreads();
        if (tid < 64) {
            float l = blog[tid];
            #pragma unroll 8
            for (int cc = 0; cc < 64; cc++) l = fmaf(pooled[cc], Wlog[cc*64 + tid], l);
            g_logits[img*64 + tid] = l;
        }
    }
}

// ---------------- pair kernel: k-packed FFMA2 GEMM, zero pack-MOVs ----------------
// One CTA per (b,j,i), 256 threads.
// smem: U[64][128], Vs[64][128], Wk[64n][128] (k-major, XOR-swizzled k-pairs),
//       H0[64][128], H1[64][128], bg2s[64].  Total 164 KB.
// Thread tile: 4 q x 4 n, n = ng + 16*ni (ng = tid&15), q = qg*4 + qi (qg = tid>>4).
// FFMA2 lanes packed over (k even, k odd).
__global__ void __launch_bounds__(256, 1) pair_k(
    const float* __restrict__ Wg2, const float* __restrict__ bg2,
    const float* __restrict__ Wf1, const float* __restrict__ bf1,
    const float* __restrict__ Wf2, const float* __restrict__ bf2) {
    extern __shared__ float sm[];
    float* U    = sm;                 // 8192  U[p][k]
    float* Vs   = sm + 8192;          // 8192  Vs[q][k]
    float* Wk   = sm + 16384;         // 8192  Wk[n][kp swizzled]
    float* H0   = sm + 24576;         // 8192
    float* H1   = sm + 32768;         // 8192
    float* bg2s = sm + 40960;         // 64

    int tid = threadIdx.x;
    int blk = blockIdx.x;
    int b = blk / 36; int r = blk - b*36; int j = r / 6; int i = r - j*6;
    const float* up = g_u + (size_t)(b*6 + i) * 8192;
    const float* vp = g_v + (size_t)(b*6 + j) * 8192;

    for (int idx = tid; idx < 8192; idx += 256) {
        U[idx]  = up[idx];
        Vs[idx] = vp[idx];
        // Wg2 natural: [k=128][n=64]. Store k-major with XOR swizzle on k-pairs:
        // Wk[n][ (kp ^ (n&15))*2 + (k&1) ]
        int n = idx & 63, k = idx >> 6;
        int kp = k >> 1;
        int phys = ((kp ^ (n & 15)) << 1) | (k & 1);
        Wk[n*128 + phys] = Wg2[idx];
    }
    if (tid < 64) bg2s[tid] = bg2[tid];
    __syncthreads();

    int ng = tid & 15, qg = tid >> 4;
    int q0 = qg * 4;
    float bb[4];
    #pragma unroll
    for (int ni = 0; ni < 4; ni++) bb[ni] = bg2s[ng + 16*ni];

    // build-phase mapping: kq = float4 column (0..31), qrow = tid>>5 (0..7)
    int kq = tid & 31, qrow = tid >> 5;

    float run[16];
    #pragma unroll
    for (int t = 0; t < 16; t++) run[t] = 0.f;

    const float4* U4  = (const float4*)U;
    const float4* Vs4 = (const float4*)Vs;
    float4* H0_4 = (float4*)H0;
    float4* H1_4 = (float4*)H1;
    const unsigned long long* Wk64 = (const unsigned long long*)Wk;

    for (int pp = 0; pp < 64; pp += 2) {
        __syncthreads();              // previous GEMM done reading H0/H1
        // ---- build H0 (p=pp), H1 (p=pp+1); share Vs loads ----
        float4 u0 = U4[pp*32 + kq];
        float4 u1 = U4[(pp+1)*32 + kq];
        #pragma unroll
        for (int t = 0; t < 8; t++) {
            int q = qrow + 8*t;
            float4 v = Vs4[q*32 + kq];
            float4 h0, h1;
            h0.x = fmaxf(u0.x + v.x, 0.f); h0.y = fmaxf(u0.y + v.y, 0.f);
            h0.z = fmaxf(u0.z + v.z, 0.f); h0.w = fmaxf(u0.w + v.w, 0.f);
            h1.x = fmaxf(u1.x + v.x, 0.f); h1.y = fmaxf(u1.y + v.y, 0.f);
            h1.z = fmaxf(u1.z + v.z, 0.f); h1.w = fmaxf(u1.w + v.w, 0.f);
            H0_4[q*32 + kq] = h0;
            H1_4[q*32 + kq] = h1;
        }
        __syncthreads();

        // ---- GEMM on H0 then H1 ----
        #pragma unroll
        for (int hb = 0; hb < 2; hb++) {
            const ulonglong2* H2 = (const ulonglong2*)(hb ? H1 : H0);
            unsigned long long acc[4][4];
            #pragma unroll
            for (int qi = 0; qi < 4; qi++)
                #pragma unroll
                for (int ni = 0; ni < 4; ni++) acc[qi][ni] = 0ull;

            #pragma unroll 4
            for (int k4 = 0; k4 < 32; k4++) {
                ulonglong2 h[4];
                #pragma unroll
                for (int qi = 0; qi < 4; qi++) h[qi] = H2[(q0+qi)*32 + k4];
                #pragma unroll
                for (int ni = 0; ni < 4; ni++) {
                    int n = ng + 16*ni;
                    unsigned long long w01 = Wk64[n*64 + ((2*k4)   ^ ng)];
                    unsigned long long w23 = Wk64[n*64 + ((2*k4+1) ^ ng)];
                    #pragma unroll
                    for (int qi = 0; qi < 4; qi++) {
                        acc[qi][ni] = fma2(h[qi].x, w01, acc[qi][ni]);
                        acc[qi][ni] = fma2(h[qi].y, w23, acc[qi][ni]);
                    }
                }
            }
            // epilogue: sum lanes + bias + relu + running sum (registers only)
            #pragma unroll
            for (int qi = 0; qi < 4; qi++)
                #pragma unroll
                for (int ni = 0; ni < 4; ni++) {
                    float e0, e1;
                    unpack2(acc[qi][ni], e0, e1);
                    run[qi*4 + ni] += fmaxf((e0 + e1) + bb[ni], 0.f);
                }
        }
    }
    __syncthreads();

    // ---- reduce run -> x_f[64] via red[n][q] (reuse Vs, stride 65) ----
    float* red = Vs;
    #pragma unroll
    for (int qi = 0; qi < 4; qi++)
        #pragma unroll
        for (int ni = 0; ni < 4; ni++)
            red[(ng + 16*ni)*65 + (q0+qi)] = run[qi*4 + ni];
    __syncthreads();
    if (tid < 64) {
        float s = 0.f;
        const float* rp = red + tid*65;
        #pragma unroll 8
        for (int q = 0; q < 64; q++) s += rp[q];
        U[tid] = s;           // x_f
    }
    __syncthreads();
    if (tid < 16) {
        float s = bf1[tid];
        for (int c = 0; c < 64; c++) s = fmaf(U[c], Wf1[c*16 + tid], s);
        H0[tid] = fmaxf(s, 0.f);
    }
    __syncthreads();
    if (tid == 0) {
        float s = bf2[0];
        for (int t2 = 0; t2 < 16; t2++) s = fmaf(H0[t2], Wf2[t2], s);
        g_score[blk] = 1.f / (1.f + __expf(-s));
    }
}

// ---------------- final losses: single block ----------------
__global__ void final_k(const int* __restrict__ sy, const int* __restrict__ qy,
                        float* __restrict__ out) {
    __shared__ float sP[144], sY[144], scls[24];
    __shared__ int slab[24];
    int tid = threadIdx.x;
    if (tid < 144) sP[tid] = g_score[tid];
    if (tid < 24) {
        int b = tid / 6, s = tid - b*6;
        slab[tid] = (s < 5) ? sy[b*5 + s] : qy[b];
    }
    __syncthreads();
    if (tid < 24) {
        const float* row = g_logits + tid*64;
        float m = row[0];
        for (int n = 1; n < 64; n++) m = fmaxf(m, row[n]);
        float se = 0.f;
        for (int n = 0; n < 64; n++) se += __expf(row[n] - m);
        float lse = m + __logf(se);
        scls[tid] = -(row[slab[tid]] - lse);
    }
    if (tid < 144) {
        int b = tid / 36, r = tid - b*36; int jj = r / 6, ii = r - jj*6;
        sY[tid] = (slab[b*6 + jj] == slab[b*6 + ii]) ? 1.f : 0.f;
    }
    __syncthreads();
    if (tid == 0) {
        float cls = 0.f;
        for (int r2 = 0; r2 < 24; r2++) cls += scls[r2];
        cls /= 24.f;
        float euc = 0.f;
        for (int t = 0; t < 144; t++) { float d = sP[t] - sY[t]; euc += d*d; }
        euc /= 144.f;
        float syml = 0.f;
        for (int b2 = 0; b2 < 4; b2++) {
            float s2 = 0.f, a2 = 0.f;
            for (int jj = 0; jj < 6; jj++)
                for (int ii = 0; ii < 6; ii++) {
                    float pa = sP[b2*36 + jj*6 + ii];
                    float pb = sP[b2*36 + ii*6 + jj];
                    float sv = 0.5f*(pa + pb), av = 0.5f*(pa - pb);
                    s2 += sv*sv; a2 += av*av;
                }
            float sn = sqrtf(s2), an = sqrtf(a2);
            syml += (sn - an) / (sn + an);
        }
        syml *= 0.25f;
        out[0] = cls;
        out[1] = euc - 0.1f * syml;
        out[2] = syml;
    }
}

// ---------------- launch ----------------
extern "C" void kernel_launch(void* const* d_in, const int* in_sizes, int n_in,
                              void* d_out, int out_size) {
    const float* sx   = (const float*)d_in[0];
    const int*   sy   = (const int*)  d_in[1];
    const float* qx   = (const float*)d_in[2];
    const int*   qy   = (const int*)  d_in[3];
    const float* k1   = (const float*)d_in[4];
    const float* bc1  = (const float*)d_in[5];
    const float* k2   = (const float*)d_in[6];
    const float* bc2  = (const float*)d_in[7];
    const float* k3   = (const float*)d_in[8];
    const float* bc3  = (const float*)d_in[9];
    const float* Wlog = (const float*)d_in[10];
    const float* blog = (const float*)d_in[11];
    const float* Wg1  = (const float*)d_in[12];
    const float* bg1  = (const float*)d_in[13];
    const float* Wg2  = (const float*)d_in[14];
    const float* bg2  = (const float*)d_in[15];
    const float* Wf1  = (const float*)d_in[16];
    const float* bf1  = (const float*)d_in[17];
    const float* Wf2  = (const float*)d_in[18];
    const float* bf2  = (const float*)d_in[19];
    float* out = (float*)d_out;

    const int pair_smem = (8192*5 + 64) * sizeof(float); // 164096 B
    cudaFuncSetAttribute(pair_k, cudaFuncAttributeMaxDynamicSharedMemorySize, pair_smem);

    conv1_k<<<3072, 256>>>(sx, qx, k1, bc1);
    conv2_k<<<1152, 256>>>(k2, bc2);
    conv3_k<<< 384, 256>>>(k3, bc3);
    uvpool_k<<<1560, 256>>>(Wg1, bg1, Wlog, blog);
    pair_k<<<144, 256, pair_smem>>>(Wg2, bg2, Wf1, bf1, Wf2, bf2);
    final_k<<<1, 160>>>(sy, qy, out);
}